// round 5
// baseline (speedup 1.0000x reference)
#include <cuda_runtime.h>
#include <cstdint>

// CausalRevIN, B=16, T=8192, C=128, f32, C innermost.
// out = clip((x-mean)/std, -100, 100); mean = cumsum(x)/n, n = max(cumsum(1-mask),1);
// std = sqrt(cumsum(((x-mean)*(1-mask))^2)/n); std<=1e-5 -> 1.
//
// v4: CHUNK 32 -> 16 (xr[] 16 regs) so 3 blocks x 512 threads fit per SM
// (75% occupancy) -- latency hiding for barriers/lookback spins. LINKS=32.

namespace {
constexpr int Bn = 16;
constexpr int Tn = 8192;
constexpr int Cn = 128;

constexpr int CS      = 32;            // channels per block (lane = channel)
constexpr int LINKS   = 32;            // T segments per chain
constexpr int TSEG    = Tn / LINKS;    // 256
constexpr int THREADS = 512;
constexpr int TPC     = THREADS / CS;  // 16 chunks per channel (warp = chunk)
constexpr int CHUNK   = TSEG / TPC;    // 16 timesteps -> 16-bit mask word
constexpr int NCG     = Cn / CS;       // 4 channel groups

constexpr int NCHAIN  = Bn * NCG * LINKS;  // 2048
} // namespace

__device__ float2   g_sxn[NCHAIN * CS];    // packed (sum_x, sum_n)
__device__ float    g_sy [NCHAIN * CS];
__device__ unsigned g_flags[2 * NCHAIN];   // [A|B][chain]

__device__ __forceinline__ unsigned ld_acquire(const unsigned* p) {
    unsigned v;
    asm volatile("ld.acquire.gpu.global.u32 %0, [%1];" : "=r"(v) : "l"(p) : "memory");
    return v;
}
__device__ __forceinline__ void st_release(unsigned* p, unsigned v) {
    asm volatile("st.release.gpu.global.u32 [%0], %1;" :: "l"(p), "r"(v) : "memory");
}

__global__ __launch_bounds__(THREADS, 3)
void crevin_kernel(const float* __restrict__ xg,
                   const float* __restrict__ mg,
                   float* __restrict__ og)
{
    __shared__ float sc_x[THREADS];
    __shared__ float sc_n[THREADS];
    __shared__ float sc_y[THREADS];
    __shared__ float bxs[CS], bns[CS], bys[CS];

    const int tid  = threadIdx.x;
    const int c    = tid & 31;        // channel within group = lane
    const int j    = tid >> 5;        // chunk index = warp id (0..15)
    const int link = blockIdx.x;      // T segment (fastest-varying bid)
    const int cg   = blockIdx.y;
    const int b    = blockIdx.z;

    const size_t gbase = ((size_t)b * Tn + (size_t)link * TSEG + j * CHUNK) * Cn
                       + cg * CS + c;
    const float* xp = xg + gbase;
    const float* mp = mg + gbase;

    // ---- phase 0: load chunk into registers, fused sums + mask bits ----
    float xr[CHUNK];
    unsigned w = 0u;
    float cx = 0.0f;
#pragma unroll
    for (int i = 0; i < CHUNK; i++) {
        const float xv = __ldcs(xp + i * Cn);
        const float mv = __ldcs(mp + i * Cn);
        xr[i] = xv;
        cx += xv;
        if (mv == 0.0f) w |= (1u << i);        // 1 = observed
    }
    const float cn = (float)__popc(w);

    // ---- local exclusive scan over the 16 chunks of each channel ----
    sc_x[j * 32 + c] = cx;
    sc_n[j * 32 + c] = cn;
    __syncthreads();
    float px = 0.0f, pn = 0.0f;
    for (int k = 0; k < j; k++) {              // j warp-uniform
        px += sc_x[k * 32 + c];
        pn += sc_n[k * 32 + c];
    }

    const int chain = (b * NCG + cg) * LINKS + link;
    const int cb    = chain - link;            // first link of this chain

    // ---- publish local totals for lookback A (no dependence on preds) ----
    if (j == TPC - 1) {
        g_sxn[chain * CS + c] = make_float2(px + cx, pn + cn);
        __threadfence();
        __syncwarp();
        if (c == 0) st_release(&g_flags[chain], 1u);
    }

    // ---- lookback A: warp 0 waits for all preds, sums totals in order ----
    if (j == 0) {
        if (link > 0) {
            for (;;) {
                unsigned f = (c < link) ? ld_acquire(&g_flags[cb + c]) : 1u;
                if (__all_sync(0xffffffffu, f != 0u)) break;
            }
        }
        float bx = 0.0f, bn = 0.0f;
        for (int p = 0; p < link; p++) {
            const float2 v = g_sxn[(cb + p) * CS + c];
            bx += v.x;
            bn += v.y;
        }
        bxs[c] = bx;
        bns[c] = bn;
    }
    __syncthreads();

    // ---- phase 2: running mean, d = x - mean (in regs), chunk sum of y ----
    float sx = bxs[c] + px;
    float sn = bns[c] + pn;
    float cy = 0.0f;
#pragma unroll
    for (int i = 0; i < CHUNK; i++) {
        const float xv = xr[i];
        const bool  ob = (w >> i) & 1u;
        sx += xv;
        if (ob) sn += 1.0f;
        const float nd   = (sn == 0.0f) ? 1.0f : sn;
        const float mean = __fdividef(sx, nd);
        const float d    = xv - mean;
        xr[i] = d;
        const float db = ob ? d : 0.0f;
        cy = fmaf(db, db, cy);
    }

    sc_y[j * 32 + c] = cy;
    __syncthreads();
    float py = 0.0f;
    for (int k = 0; k < j; k++) py += sc_y[k * 32 + c];

    // ---- publish local y totals; lookback B ----
    if (j == TPC - 1) {
        g_sy[chain * CS + c] = py + cy;
        __threadfence();
        __syncwarp();
        if (c == 0) st_release(&g_flags[NCHAIN + chain], 1u);
    }
    if (j == 0) {
        if (link > 0) {
            for (;;) {
                unsigned f = (c < link) ? ld_acquire(&g_flags[NCHAIN + cb + c]) : 1u;
                if (__all_sync(0xffffffffu, f != 0u)) break;
            }
        }
        float by = 0.0f;
        for (int p = 0; p < link; p++) by += __ldcg(&g_sy[(cb + p) * CS + c]);
        bys[c] = by;
    }
    __syncthreads();

    // ---- phase 3: running variance, normalize + clamp, coalesced store ----
    float sy  = bys[c] + py;
    float sn3 = bns[c] + pn;
    float* op = og + gbase;
#pragma unroll
    for (int i = 0; i < CHUNK; i++) {
        const float d  = xr[i];
        const bool  ob = (w >> i) & 1u;
        if (ob) sn3 += 1.0f;
        const float db = ob ? d : 0.0f;
        sy = fmaf(db, db, sy);
        const float nd  = (sn3 == 0.0f) ? 1.0f : sn3;
        const float var = __fdividef(sy, nd);
        // std > 1e-5  <=>  var > 1e-10 ; else std := 1
        const float inv_std = (var > 1e-10f) ? rsqrtf(var) : 1.0f;
        float r = d * inv_std;
        r = fminf(100.0f, fmaxf(-100.0f, r));
        __stcs(op + i * Cn, r);
    }
}

extern "C" void kernel_launch(void* const* d_in, const int* in_sizes, int n_in,
                              void* d_out, int out_size) {
    const float* x = (const float*)d_in[0];
    const float* m = (const float*)d_in[1];
    float*       o = (float*)d_out;

    static void* fptr = nullptr;
    if (!fptr) cudaGetSymbolAddress(&fptr, g_flags);
    cudaMemsetAsync(fptr, 0, sizeof(unsigned) * 2 * NCHAIN, 0);

    dim3 grid(LINKS, NCG, Bn);   // link fastest -> chain members co-resident,
                                 // preds always at lower bid (deadlock-free)
    crevin_kernel<<<grid, THREADS>>>(x, m, o);
}